// round 1
// baseline (speedup 1.0000x reference)
#include <cuda_runtime.h>

#define NNODES 100000
#define HDIM   128
#define RWS    10
#define KHOPS  4
#define CDIM   40
#define NSAMP  (KHOPS * RWS)   // 40

// Scratch ping-pong buffers (51.2 MB each) — __device__ globals, no allocation.
__device__ float g_bufA[(size_t)NNODES * HDIM];
__device__ float g_bufB[(size_t)NNODES * HDIM];

// ---------------------------------------------------------------------------
// SGEMM: C[M x 128] = A[M x K] @ W[K x 128] + bias, fp32.
// BM=128, BN=128, BK=8, 256 threads, 8x8 register micro-tile per thread.
// ---------------------------------------------------------------------------
__global__ void __launch_bounds__(256) gemm_bias_kernel(
    const float* __restrict__ A, const float* __restrict__ W,
    const float* __restrict__ bias, float* __restrict__ C,
    int M, int K)
{
    __shared__ float As[8][128];   // [k][m]  (A tile, transposed on store)
    __shared__ float Bs[8][128];   // [k][n]

    const int t  = threadIdx.x;
    const int tx = t & 15;         // column group: 16 groups x 8 cols = 128
    const int ty = t >> 4;         // row group:    16 groups x 8 rows = 128
    const int blockRow = blockIdx.x * 128;

    float acc[8][8];
    #pragma unroll
    for (int i = 0; i < 8; i++)
        #pragma unroll
        for (int j = 0; j < 8; j++) acc[i][j] = 0.0f;

    // A tile load mapping: 128 rows x 8 k per tile; each thread one float4.
    const int a_row = t >> 1;            // 0..127
    const int a_c0  = (t & 1) * 4;       // 0 or 4
    const int grow  = blockRow + a_row;
    const bool a_valid = (grow < M);
    const float* Aptr = A + (size_t)grow * K + a_c0;

    // B tile load mapping: 8 rows x 128 cols; each thread one float4.
    const int b_row = t >> 5;            // 0..7
    const int b_col = (t & 31) * 4;      // 0..124

    for (int k0 = 0; k0 < K; k0 += 8) {
        float4 av = make_float4(0.f, 0.f, 0.f, 0.f);
        if (a_valid) av = *(const float4*)(Aptr + k0);
        As[a_c0 + 0][a_row] = av.x;
        As[a_c0 + 1][a_row] = av.y;
        As[a_c0 + 2][a_row] = av.z;
        As[a_c0 + 3][a_row] = av.w;

        float4 bv = *(const float4*)(W + (size_t)(k0 + b_row) * 128 + b_col);
        *(float4*)&Bs[b_row][b_col] = bv;
        __syncthreads();

        #pragma unroll
        for (int k = 0; k < 8; k++) {
            float a[8], b[8];
            #pragma unroll
            for (int i = 0; i < 8; i++) a[i] = As[k][ty * 8 + i];
            #pragma unroll
            for (int j = 0; j < 8; j++) b[j] = Bs[k][tx * 8 + j];
            #pragma unroll
            for (int i = 0; i < 8; i++)
                #pragma unroll
                for (int j = 0; j < 8; j++)
                    acc[i][j] += a[i] * b[j];
        }
        __syncthreads();
    }

    float bb[8];
    #pragma unroll
    for (int j = 0; j < 8; j++) bb[j] = bias[tx * 8 + j];

    #pragma unroll
    for (int i = 0; i < 8; i++) {
        int row = blockRow + ty * 8 + i;
        if (row < M) {
            float* cp = C + (size_t)row * 128 + tx * 8;
            float4 v;
            v.x = acc[i][0] + bb[0]; v.y = acc[i][1] + bb[1];
            v.z = acc[i][2] + bb[2]; v.w = acc[i][3] + bb[3];
            *(float4*)cp = v;
            v.x = acc[i][4] + bb[4]; v.y = acc[i][5] + bb[5];
            v.z = acc[i][6] + bb[6]; v.w = acc[i][7] + bb[7];
            *(float4*)(cp + 4) = v;
        }
    }
}

// ---------------------------------------------------------------------------
// Random-walk aggregation + ReLU.
// One block per node, 128 threads (one per feature).
// out[n] = relu( att[0]*h[n] + sum_k att[k] * mean_r( w * h[ends[k, n*RWS+r]] ) )
// w = sqrt(deg[n]) * rsqrt(deg[e])
// ---------------------------------------------------------------------------
__global__ void __launch_bounds__(128) agg_kernel(
    const float* __restrict__ hin, float* __restrict__ hout,
    const int* __restrict__ ends_l,     // [KHOPS][NNODES*RWS]
    const float* __restrict__ deg,
    const float* __restrict__ att_l)    // [KHOPS+1]
{
    __shared__ int   se[NSAMP];
    __shared__ float sc[NSAMP];

    const int n = blockIdx.x;
    const int t = threadIdx.x;

    if (t < NSAMP) {
        const int k = t / RWS;
        const int r = t - k * RWS;
        const int e = ends_l[(size_t)k * (NNODES * RWS) + n * RWS + r];
        se[t] = e;
        sc[t] = att_l[k + 1] * (1.0f / RWS) * sqrtf(deg[n]) * rsqrtf(deg[e]);
    }
    __syncthreads();

    float acc = att_l[0] * hin[(size_t)n * HDIM + t];
    #pragma unroll
    for (int i = 0; i < NSAMP; i++) {
        acc += sc[i] * hin[(size_t)se[i] * HDIM + t];
    }
    hout[(size_t)n * HDIM + t] = fmaxf(acc, 0.0f);
}

// ---------------------------------------------------------------------------
// Final: logits = h @ W2 + b2, then log_softmax over 40 classes.
// One thread per row; W2 (128x40) staged in shared.
// ---------------------------------------------------------------------------
__global__ void __launch_bounds__(128) final_kernel(
    const float* __restrict__ h, const float* __restrict__ W2,
    const float* __restrict__ b2, float* __restrict__ out, int M)
{
    __shared__ float Ws[HDIM * CDIM];
    __shared__ float bs[CDIM];

    const int t = threadIdx.x;
    for (int i = t; i < HDIM * CDIM; i += 128) Ws[i] = W2[i];
    if (t < CDIM) bs[t] = b2[t];
    __syncthreads();

    const int row = blockIdx.x * 128 + t;
    if (row >= M) return;

    float acc[CDIM];
    #pragma unroll
    for (int c = 0; c < CDIM; c++) acc[c] = bs[c];

    const float4* hp = (const float4*)(h + (size_t)row * HDIM);
    for (int k4 = 0; k4 < HDIM / 4; k4++) {
        float4 a = hp[k4];
        const float* w0 = &Ws[(k4 * 4 + 0) * CDIM];
        const float* w1 = &Ws[(k4 * 4 + 1) * CDIM];
        const float* w2 = &Ws[(k4 * 4 + 2) * CDIM];
        const float* w3 = &Ws[(k4 * 4 + 3) * CDIM];
        #pragma unroll
        for (int c = 0; c < CDIM; c++) {
            acc[c] += a.x * w0[c];
            acc[c] += a.y * w1[c];
            acc[c] += a.z * w2[c];
            acc[c] += a.w * w3[c];
        }
    }

    float m = acc[0];
    #pragma unroll
    for (int c = 1; c < CDIM; c++) m = fmaxf(m, acc[c]);
    float s = 0.0f;
    #pragma unroll
    for (int c = 0; c < CDIM; c++) s += expf(acc[c] - m);
    const float lse = m + logf(s);

    float* op = out + (size_t)row * CDIM;
    #pragma unroll
    for (int c = 0; c < CDIM; c++) op[c] = acc[c] - lse;
}

// ---------------------------------------------------------------------------
// Launch sequence (graph-capturable: kernel launches only).
// Inputs (metadata order): x, degree, ends, att, W0, b0, W1, b1, W2, b2
// ---------------------------------------------------------------------------
extern "C" void kernel_launch(void* const* d_in, const int* in_sizes, int n_in,
                              void* d_out, int out_size)
{
    const float* x   = (const float*)d_in[0];
    const float* deg = (const float*)d_in[1];
    const int*   ends= (const int*)  d_in[2];
    const float* att = (const float*)d_in[3];
    const float* W0  = (const float*)d_in[4];
    const float* b0  = (const float*)d_in[5];
    const float* W1  = (const float*)d_in[6];
    const float* b1  = (const float*)d_in[7];
    const float* W2  = (const float*)d_in[8];
    const float* b2  = (const float*)d_in[9];
    float* out = (float*)d_out;

    float *bufA = nullptr, *bufB = nullptr;
    cudaGetSymbolAddress((void**)&bufA, g_bufA);
    cudaGetSymbolAddress((void**)&bufB, g_bufB);

    const int gridM = (NNODES + 127) / 128;   // 782

    // Layer 0: h = x @ W0 + b0  -> bufA
    gemm_bias_kernel<<<gridM, 256>>>(x, W0, b0, bufA, NNODES, 256);
    // Agg layer 0: bufA -> bufB (relu'd)
    agg_kernel<<<NNODES, 128>>>(bufA, bufB,
                                ends + 0 * (size_t)KHOPS * NNODES * RWS,
                                deg, att + 0 * (KHOPS + 1));
    // Layer 1: h = bufB @ W1 + b1 -> bufA
    gemm_bias_kernel<<<gridM, 256>>>(bufB, W1, b1, bufA, NNODES, 128);
    // Agg layer 1: bufA -> bufB (relu'd)
    agg_kernel<<<NNODES, 128>>>(bufA, bufB,
                                ends + 1 * (size_t)KHOPS * NNODES * RWS,
                                deg, att + 1 * (KHOPS + 1));
    // Final: logits + log_softmax -> out
    final_kernel<<<gridM, 128>>>(bufB, W2, b2, out, NNODES);
}

// round 2
// speedup vs baseline: 1.1286x; 1.1286x over previous
#include <cuda_runtime.h>

#define NNODES 100000
#define HDIM   128
#define RWS    10
#define KHOPS  4
#define CDIM   40
#define NSAMP  (KHOPS * RWS)   // 40
#define NPB    4               // nodes per agg block (32 lanes each)

// Scratch ping-pong buffers (51.2 MB each) — __device__ globals, no allocation.
__device__ float g_bufA[(size_t)NNODES * HDIM];
__device__ float g_bufB[(size_t)NNODES * HDIM];

// ---------------------------------------------------------------------------
// SGEMM: C[M x 128] = A[M x K] @ W[K x 128] + bias, fp32.
// BM=128, BN=128, BK=8, 256 threads, 8x8 micro-tile, double-buffered smem.
// ---------------------------------------------------------------------------
__global__ void __launch_bounds__(256) gemm_bias_kernel(
    const float* __restrict__ A, const float* __restrict__ W,
    const float* __restrict__ bias, float* __restrict__ C,
    int M, int K)
{
    __shared__ float As[2][8][128];   // [buf][k][m]
    __shared__ float Bs[2][8][128];   // [buf][k][n]

    const int t  = threadIdx.x;
    const int tx = t & 15;         // 16 column groups x 8 cols
    const int ty = t >> 4;         // 16 row groups x 8 rows
    const int blockRow = blockIdx.x * 128;

    float acc[8][8];
    #pragma unroll
    for (int i = 0; i < 8; i++)
        #pragma unroll
        for (int j = 0; j < 8; j++) acc[i][j] = 0.0f;

    // A tile load: 128 rows x 8 k; one float4 per thread.
    const int a_row = t >> 1;
    const int a_c0  = (t & 1) * 4;
    const int grow  = blockRow + a_row;
    const bool a_valid = (grow < M);
    const float* Aptr = A + (size_t)grow * K + a_c0;

    // B tile load: 8 rows x 128 cols; one float4 per thread.
    const int b_row = t >> 5;
    const int b_col = (t & 31) * 4;

    // Prologue: load tile 0.
    {
        float4 av = make_float4(0.f, 0.f, 0.f, 0.f);
        if (a_valid) av = *(const float4*)(Aptr);
        As[0][a_c0 + 0][a_row] = av.x;
        As[0][a_c0 + 1][a_row] = av.y;
        As[0][a_c0 + 2][a_row] = av.z;
        As[0][a_c0 + 3][a_row] = av.w;
        float4 bv = *(const float4*)(W + (size_t)b_row * 128 + b_col);
        *(float4*)&Bs[0][b_row][b_col] = bv;
    }
    __syncthreads();

    int buf = 0;
    for (int k0 = 0; k0 < K; k0 += 8) {
        const bool has_next = (k0 + 8 < K);
        float4 av_n = make_float4(0.f, 0.f, 0.f, 0.f);
        float4 bv_n;
        if (has_next) {
            if (a_valid) av_n = *(const float4*)(Aptr + k0 + 8);
            bv_n = *(const float4*)(W + (size_t)(k0 + 8 + b_row) * 128 + b_col);
        }

        #pragma unroll
        for (int k = 0; k < 8; k++) {
            float a[8], b[8];
            #pragma unroll
            for (int i = 0; i < 8; i++) a[i] = As[buf][k][ty * 8 + i];
            #pragma unroll
            for (int j = 0; j < 8; j++) b[j] = Bs[buf][k][tx * 8 + j];
            #pragma unroll
            for (int i = 0; i < 8; i++)
                #pragma unroll
                for (int j = 0; j < 8; j++)
                    acc[i][j] += a[i] * b[j];
        }

        if (has_next) {
            const int nb = buf ^ 1;
            As[nb][a_c0 + 0][a_row] = av_n.x;
            As[nb][a_c0 + 1][a_row] = av_n.y;
            As[nb][a_c0 + 2][a_row] = av_n.z;
            As[nb][a_c0 + 3][a_row] = av_n.w;
            *(float4*)&Bs[nb][b_row][b_col] = bv_n;
            __syncthreads();
            buf = nb;
        }
    }

    float bb[8];
    #pragma unroll
    for (int j = 0; j < 8; j++) bb[j] = bias[tx * 8 + j];

    #pragma unroll
    for (int i = 0; i < 8; i++) {
        int row = blockRow + ty * 8 + i;
        if (row < M) {
            float* cp = C + (size_t)row * 128 + tx * 8;
            float4 v;
            v.x = acc[i][0] + bb[0]; v.y = acc[i][1] + bb[1];
            v.z = acc[i][2] + bb[2]; v.w = acc[i][3] + bb[3];
            *(float4*)cp = v;
            v.x = acc[i][4] + bb[4]; v.y = acc[i][5] + bb[5];
            v.z = acc[i][6] + bb[6]; v.w = acc[i][7] + bb[7];
            *(float4*)(cp + 4) = v;
        }
    }
}

// ---------------------------------------------------------------------------
// Random-walk aggregation + ReLU, float4-vectorized.
// 128 threads = 4 nodes x 32 lanes; each lane owns 4 features (float4).
// out[n] = relu( att[0]*h[n] + sum_s sc_s * h[e_s] )
// sc_s = att[k+1]/RWS * sqrt(deg[n]) * rsqrt(deg[e_s])
// ---------------------------------------------------------------------------
__global__ void __launch_bounds__(128) agg_kernel(
    const float4* __restrict__ hin, float4* __restrict__ hout,
    const int* __restrict__ ends_l,     // [KHOPS][NNODES*RWS]
    const float* __restrict__ deg,
    const float* __restrict__ att_l)    // [KHOPS+1]
{
    __shared__ int   se[NPB][NSAMP];
    __shared__ float sc[NPB][NSAMP];

    const int n0 = blockIdx.x * NPB;
    const int t  = threadIdx.x;

    // Stage 160 (node,sample) entries: endpoint index + combined scale.
    #pragma unroll
    for (int i = t; i < NPB * NSAMP; i += 128) {
        const int nl = i / NSAMP;
        const int s  = i - nl * NSAMP;
        const int k  = s / RWS;
        const int r  = s - k * RWS;
        const int n  = n0 + nl;
        const int e  = ends_l[k * (NNODES * RWS) + n * RWS + r];
        se[nl][s] = e;
        sc[nl][s] = att_l[k + 1] * (1.0f / RWS) * sqrtf(deg[n]) * rsqrtf(deg[e]);
    }
    __syncthreads();

    const int nl   = t >> 5;
    const int lane = t & 31;
    const int n    = n0 + nl;

    const float att0 = att_l[0];
    float4 hv = hin[n * 32 + lane];
    float4 acc;
    acc.x = att0 * hv.x; acc.y = att0 * hv.y;
    acc.z = att0 * hv.z; acc.w = att0 * hv.w;

    #pragma unroll 8
    for (int i = 0; i < NSAMP; i++) {
        const float  w = sc[nl][i];
        const float4 v = hin[se[nl][i] * 32 + lane];
        acc.x += w * v.x; acc.y += w * v.y;
        acc.z += w * v.z; acc.w += w * v.w;
    }

    acc.x = fmaxf(acc.x, 0.0f); acc.y = fmaxf(acc.y, 0.0f);
    acc.z = fmaxf(acc.z, 0.0f); acc.w = fmaxf(acc.w, 0.0f);
    hout[n * 32 + lane] = acc;
}

// ---------------------------------------------------------------------------
// Final: logits = h @ W2 + b2, then log_softmax over 40 classes.
// One thread per row; W2 (128x40) staged in shared; fast-math exp/log.
// ---------------------------------------------------------------------------
__global__ void __launch_bounds__(128) final_kernel(
    const float* __restrict__ h, const float* __restrict__ W2,
    const float* __restrict__ b2, float* __restrict__ out, int M)
{
    __shared__ float Ws[HDIM * CDIM];
    __shared__ float bs[CDIM];

    const int t = threadIdx.x;
    for (int i = t; i < HDIM * CDIM; i += 128) Ws[i] = W2[i];
    if (t < CDIM) bs[t] = b2[t];
    __syncthreads();

    const int row = blockIdx.x * 128 + t;
    if (row >= M) return;

    float acc[CDIM];
    #pragma unroll
    for (int c = 0; c < CDIM; c++) acc[c] = bs[c];

    const float4* hp = (const float4*)(h + (size_t)row * HDIM);
    for (int k4 = 0; k4 < HDIM / 4; k4++) {
        float4 a = hp[k4];
        const float* w0 = &Ws[(k4 * 4 + 0) * CDIM];
        const float* w1 = &Ws[(k4 * 4 + 1) * CDIM];
        const float* w2 = &Ws[(k4 * 4 + 2) * CDIM];
        const float* w3 = &Ws[(k4 * 4 + 3) * CDIM];
        #pragma unroll
        for (int c = 0; c < CDIM; c++) {
            acc[c] += a.x * w0[c];
            acc[c] += a.y * w1[c];
            acc[c] += a.z * w2[c];
            acc[c] += a.w * w3[c];
        }
    }

    float m = acc[0];
    #pragma unroll
    for (int c = 1; c < CDIM; c++) m = fmaxf(m, acc[c]);
    float s = 0.0f;
    #pragma unroll
    for (int c = 0; c < CDIM; c++) s += __expf(acc[c] - m);
    const float lse = m + __logf(s);

    float* op = out + (size_t)row * CDIM;
    #pragma unroll
    for (int c = 0; c < CDIM; c++) op[c] = acc[c] - lse;
}

// ---------------------------------------------------------------------------
// Launch sequence (graph-capturable: kernel launches only).
// Inputs (metadata order): x, degree, ends, att, W0, b0, W1, b1, W2, b2
// ---------------------------------------------------------------------------
extern "C" void kernel_launch(void* const* d_in, const int* in_sizes, int n_in,
                              void* d_out, int out_size)
{
    const float* x   = (const float*)d_in[0];
    const float* deg = (const float*)d_in[1];
    const int*   ends= (const int*)  d_in[2];
    const float* att = (const float*)d_in[3];
    const float* W0  = (const float*)d_in[4];
    const float* b0  = (const float*)d_in[5];
    const float* W1  = (const float*)d_in[6];
    const float* b1  = (const float*)d_in[7];
    const float* W2  = (const float*)d_in[8];
    const float* b2  = (const float*)d_in[9];
    float* out = (float*)d_out;

    float *bufA = nullptr, *bufB = nullptr;
    cudaGetSymbolAddress((void**)&bufA, g_bufA);
    cudaGetSymbolAddress((void**)&bufB, g_bufB);

    const int gridM   = (NNODES + 127) / 128;     // 782
    const int gridAgg = NNODES / NPB;             // 25000

    // Layer 0: h = x @ W0 + b0  -> bufA
    gemm_bias_kernel<<<gridM, 256>>>(x, W0, b0, bufA, NNODES, 256);
    // Agg layer 0: bufA -> bufB (relu'd)
    agg_kernel<<<gridAgg, 128>>>((const float4*)bufA, (float4*)bufB,
                                 ends + 0 * (size_t)KHOPS * NNODES * RWS,
                                 deg, att + 0 * (KHOPS + 1));
    // Layer 1: h = bufB @ W1 + b1 -> bufA
    gemm_bias_kernel<<<gridM, 256>>>(bufB, W1, b1, bufA, NNODES, 128);
    // Agg layer 1: bufA -> bufB (relu'd)
    agg_kernel<<<gridAgg, 128>>>((const float4*)bufA, (float4*)bufB,
                                 ends + 1 * (size_t)KHOPS * NNODES * RWS,
                                 deg, att + 1 * (KHOPS + 1));
    // Final: logits + log_softmax -> out
    final_kernel<<<gridM, 128>>>(bufB, W2, b2, out, NNODES);
}

// round 3
// speedup vs baseline: 1.3935x; 1.2347x over previous
#include <cuda_runtime.h>
#include <cuda_fp16.h>

#define NNODES 100000
#define HDIM   128
#define RWS    10
#define KHOPS  4
#define CDIM   40
#define NSAMP  (KHOPS * RWS)   // 40
#define NPB    8               // nodes per agg block (16 lanes each)

// Scratch ping-pong buffers in fp16 (25.6 MB each) — __device__ globals.
__device__ __half g_bufA[(size_t)NNODES * HDIM];
__device__ __half g_bufB[(size_t)NNODES * HDIM];

__device__ __forceinline__ void h8_to_f8(uint4 r, float* f) {
    float2 v;
    v = __half22float2(*(__half2*)&r.x); f[0] = v.x; f[1] = v.y;
    v = __half22float2(((__half2*)&r.x)[1]); f[2] = v.x; f[3] = v.y;
    v = __half22float2(*(__half2*)&r.z); f[4] = v.x; f[5] = v.y;
    v = __half22float2(((__half2*)&r.z)[1]); f[6] = v.x; f[7] = v.y;
}

__device__ __forceinline__ uint4 f8_to_h8(const float* f) {
    uint4 r;
    ((__half2*)&r.x)[0] = __floats2half2_rn(f[0], f[1]);
    ((__half2*)&r.x)[1] = __floats2half2_rn(f[2], f[3]);
    ((__half2*)&r.z)[0] = __floats2half2_rn(f[4], f[5]);
    ((__half2*)&r.z)[1] = __floats2half2_rn(f[6], f[7]);
    return r;
}

// ---------------------------------------------------------------------------
// SGEMM: C[M x 128] = A[M x K] @ W[K x 128] + bias. A fp32 or fp16, C fp16.
// BM=128, BN=128, BK=8, 256 threads, 8x8 micro-tile, double-buffered smem.
// ---------------------------------------------------------------------------
template <typename TA>
__global__ void __launch_bounds__(256) gemm_bias_kernel(
    const TA* __restrict__ A, const float* __restrict__ W,
    const float* __restrict__ bias, __half* __restrict__ C,
    int M, int K)
{
    __shared__ float As[2][8][128];   // [buf][k][m]
    __shared__ float Bs[2][8][128];   // [buf][k][n]

    const int t  = threadIdx.x;
    const int tx = t & 15;
    const int ty = t >> 4;
    const int blockRow = blockIdx.x * 128;

    float acc[8][8];
    #pragma unroll
    for (int i = 0; i < 8; i++)
        #pragma unroll
        for (int j = 0; j < 8; j++) acc[i][j] = 0.0f;

    // A tile: 128 rows x 8 k; each thread 4 consecutive k of one row.
    const int a_row = t >> 1;
    const int a_c0  = (t & 1) * 4;
    const int grow  = blockRow + a_row;
    const bool a_valid = (grow < M);
    const TA* Aptr = A + (size_t)grow * K + a_c0;

    // B tile: 8 rows x 128 cols; one float4 per thread.
    const int b_row = t >> 5;
    const int b_col = (t & 31) * 4;

    auto loadA4 = [&](int koff, float* out) {
        if (!a_valid) { out[0] = out[1] = out[2] = out[3] = 0.f; return; }
        if constexpr (sizeof(TA) == 4) {
            float4 v = *(const float4*)((const float*)Aptr + koff);
            out[0] = v.x; out[1] = v.y; out[2] = v.z; out[3] = v.w;
        } else {
            uint2 rv = *(const uint2*)((const __half*)Aptr + koff);
            float2 v0 = __half22float2(*(__half2*)&rv.x);
            float2 v1 = __half22float2(*(__half2*)&rv.y);
            out[0] = v0.x; out[1] = v0.y; out[2] = v1.x; out[3] = v1.y;
        }
    };

    // Prologue: tile 0.
    {
        float av[4]; loadA4(0, av);
        #pragma unroll
        for (int q = 0; q < 4; q++) As[0][a_c0 + q][a_row] = av[q];
        float4 bv = *(const float4*)(W + (size_t)b_row * 128 + b_col);
        *(float4*)&Bs[0][b_row][b_col] = bv;
    }
    __syncthreads();

    int buf = 0;
    for (int k0 = 0; k0 < K; k0 += 8) {
        const bool has_next = (k0 + 8 < K);
        float av_n[4];
        float4 bv_n;
        if (has_next) {
            loadA4(k0 + 8, av_n);
            bv_n = *(const float4*)(W + (size_t)(k0 + 8 + b_row) * 128 + b_col);
        }

        #pragma unroll
        for (int k = 0; k < 8; k++) {
            float a[8], b[8];
            #pragma unroll
            for (int i = 0; i < 8; i++) a[i] = As[buf][k][ty * 8 + i];
            #pragma unroll
            for (int j = 0; j < 8; j++) b[j] = Bs[buf][k][tx * 8 + j];
            #pragma unroll
            for (int i = 0; i < 8; i++)
                #pragma unroll
                for (int j = 0; j < 8; j++)
                    acc[i][j] += a[i] * b[j];
        }

        if (has_next) {
            const int nb = buf ^ 1;
            #pragma unroll
            for (int q = 0; q < 4; q++) As[nb][a_c0 + q][a_row] = av_n[q];
            *(float4*)&Bs[nb][b_row][b_col] = bv_n;
            __syncthreads();
            buf = nb;
        }
    }

    float bb[8];
    #pragma unroll
    for (int j = 0; j < 8; j++) bb[j] = bias[tx * 8 + j];

    #pragma unroll
    for (int i = 0; i < 8; i++) {
        int row = blockRow + ty * 8 + i;
        if (row < M) {
            float f[8];
            #pragma unroll
            for (int j = 0; j < 8; j++) f[j] = acc[i][j] + bb[j];
            *(uint4*)(C + (size_t)row * 128 + tx * 8) = f8_to_h8(f);
        }
    }
}

// ---------------------------------------------------------------------------
// Random-walk aggregation + ReLU, fp16 storage, fp32 accumulate.
// 128 threads = 8 nodes x 16 lanes; each lane owns 8 features (16B row slice).
// ---------------------------------------------------------------------------
__global__ void __launch_bounds__(128) agg_kernel(
    const __half* __restrict__ hin, __half* __restrict__ hout,
    const int* __restrict__ ends_l,     // [KHOPS][NNODES*RWS]
    const float* __restrict__ deg,
    const float* __restrict__ att_l)    // [KHOPS+1]
{
    __shared__ int   se[NPB][NSAMP];
    __shared__ float sc[NPB][NSAMP];

    const int n0 = blockIdx.x * NPB;
    const int t  = threadIdx.x;

    // Stage 320 (node,sample) entries.
    #pragma unroll
    for (int i = t; i < NPB * NSAMP; i += 128) {
        const int nl = i / NSAMP;
        const int s  = i - nl * NSAMP;
        const int k  = s / RWS;
        const int r  = s - k * RWS;
        const int n  = n0 + nl;
        const int e  = ends_l[k * (NNODES * RWS) + n * RWS + r];
        se[nl][s] = e;
        sc[nl][s] = att_l[k + 1] * (1.0f / RWS) * sqrtf(deg[n]) * rsqrtf(deg[e]);
    }
    __syncthreads();

    const int nl   = t >> 4;
    const int lane = t & 15;
    const int n    = n0 + nl;

    const float att0 = att_l[0];
    float acc[8], f[8];
    {
        uint4 raw = *(const uint4*)(hin + (size_t)n * HDIM + lane * 8);
        h8_to_f8(raw, f);
        #pragma unroll
        for (int q = 0; q < 8; q++) acc[q] = att0 * f[q];
    }

    #pragma unroll 8
    for (int s = 0; s < NSAMP; s++) {
        const float w = sc[nl][s];
        uint4 raw = *(const uint4*)(hin + (size_t)se[nl][s] * HDIM + lane * 8);
        h8_to_f8(raw, f);
        #pragma unroll
        for (int q = 0; q < 8; q++) acc[q] += w * f[q];
    }

    #pragma unroll
    for (int q = 0; q < 8; q++) acc[q] = fmaxf(acc[q], 0.0f);
    *(uint4*)(hout + (size_t)n * HDIM + lane * 8) = f8_to_h8(acc);
}

// ---------------------------------------------------------------------------
// Final: logits = h @ W2 + b2, then log_softmax over 40 classes.
// One thread per row (fp16 h); W2 staged in shared, float4-broadcast reads.
// ---------------------------------------------------------------------------
__global__ void __launch_bounds__(128) final_kernel(
    const __half* __restrict__ h, const float* __restrict__ W2,
    const float* __restrict__ b2, float* __restrict__ out, int M)
{
    __shared__ float Ws[HDIM * CDIM];
    __shared__ float bs[CDIM];

    const int t = threadIdx.x;
    for (int i = t; i < HDIM * CDIM; i += 128) Ws[i] = W2[i];
    if (t < CDIM) bs[t] = b2[t];
    __syncthreads();

    const int row = blockIdx.x * 128 + t;
    if (row >= M) return;

    float acc[CDIM];
    #pragma unroll
    for (int c = 0; c < CDIM; c++) acc[c] = bs[c];

    const uint4* hp = (const uint4*)(h + (size_t)row * HDIM);  // 16 x 8 halves
    for (int kc = 0; kc < HDIM / 8; kc++) {
        float f[8];
        h8_to_f8(hp[kc], f);
        #pragma unroll
        for (int kk = 0; kk < 8; kk++) {
            const float a = f[kk];
            const float* wr = &Ws[(kc * 8 + kk) * CDIM];
            #pragma unroll
            for (int c4 = 0; c4 < CDIM / 4; c4++) {
                float4 w = *(const float4*)&wr[c4 * 4];
                acc[c4 * 4 + 0] += a * w.x;
                acc[c4 * 4 + 1] += a * w.y;
                acc[c4 * 4 + 2] += a * w.z;
                acc[c4 * 4 + 3] += a * w.w;
            }
        }
    }

    float m = acc[0];
    #pragma unroll
    for (int c = 1; c < CDIM; c++) m = fmaxf(m, acc[c]);
    float s = 0.0f;
    #pragma unroll
    for (int c = 0; c < CDIM; c++) s += __expf(acc[c] - m);
    const float lse = m + __logf(s);

    float* op = out + (size_t)row * CDIM;
    #pragma unroll
    for (int c = 0; c < CDIM; c++) op[c] = acc[c] - lse;
}

// ---------------------------------------------------------------------------
// Launch sequence. Inputs: x, degree, ends, att, W0, b0, W1, b1, W2, b2
// ---------------------------------------------------------------------------
extern "C" void kernel_launch(void* const* d_in, const int* in_sizes, int n_in,
                              void* d_out, int out_size)
{
    const float* x   = (const float*)d_in[0];
    const float* deg = (const float*)d_in[1];
    const int*   ends= (const int*)  d_in[2];
    const float* att = (const float*)d_in[3];
    const float* W0  = (const float*)d_in[4];
    const float* b0  = (const float*)d_in[5];
    const float* W1  = (const float*)d_in[6];
    const float* b1  = (const float*)d_in[7];
    const float* W2  = (const float*)d_in[8];
    const float* b2  = (const float*)d_in[9];
    float* out = (float*)d_out;

    __half *bufA = nullptr, *bufB = nullptr;
    cudaGetSymbolAddress((void**)&bufA, g_bufA);
    cudaGetSymbolAddress((void**)&bufB, g_bufB);

    const int gridM   = (NNODES + 127) / 128;     // 782
    const int gridAgg = NNODES / NPB;             // 12500

    // Layer 0: h = x @ W0 + b0  -> bufA (fp16)
    gemm_bias_kernel<float><<<gridM, 256>>>(x, W0, b0, bufA, NNODES, 256);
    // Agg layer 0: bufA -> bufB (relu'd)
    agg_kernel<<<gridAgg, 128>>>(bufA, bufB,
                                 ends + 0 * (size_t)KHOPS * NNODES * RWS,
                                 deg, att + 0 * (KHOPS + 1));
    // Layer 1: h = bufB @ W1 + b1 -> bufA (fp16)
    gemm_bias_kernel<__half><<<gridM, 256>>>(bufB, W1, b1, bufA, NNODES, 128);
    // Agg layer 1: bufA -> bufB (relu'd)
    agg_kernel<<<gridAgg, 128>>>(bufA, bufB,
                                 ends + 1 * (size_t)KHOPS * NNODES * RWS,
                                 deg, att + 1 * (KHOPS + 1));
    // Final: logits + log_softmax -> out
    final_kernel<<<gridM, 128>>>(bufB, W2, b2, out, NNODES);
}

// round 4
// speedup vs baseline: 2.0965x; 1.5045x over previous
#include <cuda_runtime.h>
#include <cuda_fp16.h>
#include <cstdint>

#define NNODES 100000
#define HDIM   128
#define RWS    10
#define KHOPS  4
#define CDIM   40
#define NSAMP  (KHOPS * RWS)   // 40
#define NPB    8               // nodes per agg block (16 lanes each)

// Scratch ping-pong buffers in fp16 (25.6 MB each) — __device__ globals.
__device__ __half g_bufA[(size_t)NNODES * HDIM];
__device__ __half g_bufB[(size_t)NNODES * HDIM];

__device__ __forceinline__ void h8_to_f8(uint4 r, float* f) {
    float2 v;
    v = __half22float2(*(__half2*)&r.x); f[0] = v.x; f[1] = v.y;
    v = __half22float2(((__half2*)&r.x)[1]); f[2] = v.x; f[3] = v.y;
    v = __half22float2(*(__half2*)&r.z); f[4] = v.x; f[5] = v.y;
    v = __half22float2(((__half2*)&r.z)[1]); f[6] = v.x; f[7] = v.y;
}

__device__ __forceinline__ uint4 f8_to_h8(const float* f) {
    uint4 r;
    ((__half2*)&r.x)[0] = __floats2half2_rn(f[0], f[1]);
    ((__half2*)&r.x)[1] = __floats2half2_rn(f[2], f[3]);
    ((__half2*)&r.z)[0] = __floats2half2_rn(f[4], f[5]);
    ((__half2*)&r.z)[1] = __floats2half2_rn(f[6], f[7]);
    return r;
}

// ---------------------------------------------------------------------------
// Tensor-core primitives (warp-level mma path)
// ---------------------------------------------------------------------------
__device__ __forceinline__ uint32_t smem_u32(const void* p) {
    return (uint32_t)__cvta_generic_to_shared(p);
}
__device__ __forceinline__ void ldsm_x4(uint32_t* r, uint32_t a) {
    asm volatile("ldmatrix.sync.aligned.m8n8.x4.shared.b16 {%0,%1,%2,%3}, [%4];"
                 : "=r"(r[0]), "=r"(r[1]), "=r"(r[2]), "=r"(r[3]) : "r"(a));
}
__device__ __forceinline__ void ldsm_x4_t(uint32_t* r, uint32_t a) {
    asm volatile("ldmatrix.sync.aligned.m8n8.x4.trans.shared.b16 {%0,%1,%2,%3}, [%4];"
                 : "=r"(r[0]), "=r"(r[1]), "=r"(r[2]), "=r"(r[3]) : "r"(a));
}
__device__ __forceinline__ void mma16816(float* c, const uint32_t* a, const uint32_t* b) {
    asm volatile(
        "mma.sync.aligned.m16n8k16.row.col.f32.f16.f16.f32 "
        "{%0,%1,%2,%3}, {%4,%5,%6,%7}, {%8,%9}, {%0,%1,%2,%3};"
        : "+f"(c[0]), "+f"(c[1]), "+f"(c[2]), "+f"(c[3])
        : "r"(a[0]), "r"(a[1]), "r"(a[2]), "r"(a[3]), "r"(b[0]), "r"(b[1]));
}

// ---------------------------------------------------------------------------
// HMMA GEMM: C[M x 128] = A[M x K] @ W[K x 128] + bias.
// A fp32 or fp16 (converted to fp16 on smem store), W fp32 (converted),
// fp32 accumulate, fp16 C. BM=128, BN=128, BK=16, 8 warps (4x2), 32x64/warp.
// ---------------------------------------------------------------------------
template <typename TA>
__global__ void __launch_bounds__(256) hgemm_kernel(
    const TA* __restrict__ A, const float* __restrict__ W,
    const float* __restrict__ bias, __half* __restrict__ C,
    int M, int K)
{
    constexpr int AP = 24;   // As row pitch in halves (48 B, conflict-free)
    constexpr int BP = 136;  // Bs row pitch in halves (272 B, conflict-free)
    __shared__ __half As[2][128 * AP];
    __shared__ __half Bs[2][16 * BP];

    const int t    = threadIdx.x;
    const int lane = t & 31;
    const int wid  = t >> 5;
    const int warpRow = wid >> 1;     // 0..3 -> 32-row slab
    const int warpCol = wid & 1;      // 0..1 -> 64-col slab
    const int blockRow = blockIdx.x * 128;

    // A staging: thread -> (row 0..127, kgroup 0/8), 8 halves each.
    const int a_row = t >> 1;
    const int a_kg  = (t & 1) * 8;
    const int grow  = blockRow + a_row;
    const bool a_valid = (grow < M);

    // B staging: thread -> (k-row 0..15, 8 cols), 8 halves each.
    const int b_r = t >> 4;
    const int b_n = (t & 15) * 8;

    float acc[2][8][4];
    #pragma unroll
    for (int mt = 0; mt < 2; mt++)
        #pragma unroll
        for (int nt = 0; nt < 8; nt++)
            #pragma unroll
            for (int q = 0; q < 4; q++) acc[mt][nt][q] = 0.0f;

    auto loadA = [&](int buf, int k0) {
        __half h8[8];
        if (a_valid) {
            if constexpr (sizeof(TA) == 4) {
                const float* p = (const float*)A + (size_t)grow * K + k0 + a_kg;
                float4 v0 = *(const float4*)p;
                float4 v1 = *(const float4*)(p + 4);
                h8[0] = __float2half_rn(v0.x); h8[1] = __float2half_rn(v0.y);
                h8[2] = __float2half_rn(v0.z); h8[3] = __float2half_rn(v0.w);
                h8[4] = __float2half_rn(v1.x); h8[5] = __float2half_rn(v1.y);
                h8[6] = __float2half_rn(v1.z); h8[7] = __float2half_rn(v1.w);
            } else {
                const __half* p = (const __half*)A + (size_t)grow * K + k0 + a_kg;
                *(uint4*)h8 = *(const uint4*)p;
            }
        } else {
            #pragma unroll
            for (int q = 0; q < 8; q++) h8[q] = __float2half_rn(0.0f);
        }
        *(uint4*)&As[buf][a_row * AP + a_kg] = *(uint4*)h8;
    };

    auto loadB = [&](int buf, int k0) {
        const float* p = W + (size_t)(k0 + b_r) * 128 + b_n;
        float4 v0 = *(const float4*)p;
        float4 v1 = *(const float4*)(p + 4);
        __half h8[8];
        h8[0] = __float2half_rn(v0.x); h8[1] = __float2half_rn(v0.y);
        h8[2] = __float2half_rn(v0.z); h8[3] = __float2half_rn(v0.w);
        h8[4] = __float2half_rn(v1.x); h8[5] = __float2half_rn(v1.y);
        h8[6] = __float2half_rn(v1.z); h8[7] = __float2half_rn(v1.w);
        *(uint4*)&Bs[buf][b_r * BP + b_n] = *(uint4*)h8;
    };

    loadA(0, 0);
    loadB(0, 0);
    __syncthreads();

    // ldmatrix lane addressing (computed once)
    const int a_lr = lane & 15;               // row within m16 tile
    const int a_lk = (lane >> 4) * 8;         // k-half selector
    const int b_lr = (lane & 7) + ((lane >> 3) & 1) * 8;   // k-row 0..15
    const int b_lcg = (lane >> 4) * 8;        // n-subtile selector

    int buf = 0;
    for (int k0 = 0; k0 < K; k0 += 16) {
        const bool has_next = (k0 + 16 < K);
        if (has_next) {
            loadA(buf ^ 1, k0 + 16);
            loadB(buf ^ 1, k0 + 16);
        }

        uint32_t a[2][4];
        #pragma unroll
        for (int mt = 0; mt < 2; mt++) {
            uint32_t addr = smem_u32(
                &As[buf][(warpRow * 32 + mt * 16 + a_lr) * AP + a_lk]);
            ldsm_x4(a[mt], addr);
        }

        uint32_t b[8][2];
        #pragma unroll
        for (int ntp = 0; ntp < 4; ntp++) {
            uint32_t r4[4];
            uint32_t addr = smem_u32(
                &Bs[buf][b_lr * BP + warpCol * 64 + ntp * 16 + b_lcg]);
            ldsm_x4_t(r4, addr);
            b[ntp * 2 + 0][0] = r4[0]; b[ntp * 2 + 0][1] = r4[1];
            b[ntp * 2 + 1][0] = r4[2]; b[ntp * 2 + 1][1] = r4[3];
        }

        #pragma unroll
        for (int mt = 0; mt < 2; mt++)
            #pragma unroll
            for (int nt = 0; nt < 8; nt++)
                mma16816(acc[mt][nt], a[mt], b[nt]);

        if (has_next) {
            __syncthreads();
            buf ^= 1;
        }
    }

    // Epilogue: add bias (fp32), store fp16 half2.
    float2 bb[8];
    #pragma unroll
    for (int nt = 0; nt < 8; nt++) {
        const int col = warpCol * 64 + nt * 8 + (lane & 3) * 2;
        bb[nt] = *(const float2*)&bias[col];
    }

    #pragma unroll
    for (int mt = 0; mt < 2; mt++) {
        const int r0 = blockRow + warpRow * 32 + mt * 16 + (lane >> 2);
        const int r1 = r0 + 8;
        #pragma unroll
        for (int nt = 0; nt < 8; nt++) {
            const int col = warpCol * 64 + nt * 8 + (lane & 3) * 2;
            if (r0 < M) {
                __half2 v = __floats2half2_rn(acc[mt][nt][0] + bb[nt].x,
                                              acc[mt][nt][1] + bb[nt].y);
                *(__half2*)(C + (size_t)r0 * 128 + col) = v;
            }
            if (r1 < M) {
                __half2 v = __floats2half2_rn(acc[mt][nt][2] + bb[nt].x,
                                              acc[mt][nt][3] + bb[nt].y);
                *(__half2*)(C + (size_t)r1 * 128 + col) = v;
            }
        }
    }
}

// ---------------------------------------------------------------------------
// Random-walk aggregation + ReLU, fp16 storage, fp32 accumulate.
// 128 threads = 8 nodes x 16 lanes; each lane owns 8 features (16B slice).
// ---------------------------------------------------------------------------
__global__ void __launch_bounds__(128) agg_kernel(
    const __half* __restrict__ hin, __half* __restrict__ hout,
    const int* __restrict__ ends_l,     // [KHOPS][NNODES*RWS]
    const float* __restrict__ deg,
    const float* __restrict__ att_l)    // [KHOPS+1]
{
    __shared__ int   se[NPB][NSAMP];
    __shared__ float sc[NPB][NSAMP];

    const int n0 = blockIdx.x * NPB;
    const int t  = threadIdx.x;

    #pragma unroll
    for (int i = t; i < NPB * NSAMP; i += 128) {
        const int nl = i / NSAMP;
        const int s  = i - nl * NSAMP;
        const int k  = s / RWS;
        const int r  = s - k * RWS;
        const int n  = n0 + nl;
        const int e  = ends_l[k * (NNODES * RWS) + n * RWS + r];
        se[nl][s] = e;
        sc[nl][s] = att_l[k + 1] * (1.0f / RWS) * sqrtf(deg[n]) * rsqrtf(deg[e]);
    }
    __syncthreads();

    const int nl   = t >> 4;
    const int lane = t & 15;
    const int n    = n0 + nl;

    const float att0 = att_l[0];
    float acc[8], f[8];
    {
        uint4 raw = *(const uint4*)(hin + (size_t)n * HDIM + lane * 8);
        h8_to_f8(raw, f);
        #pragma unroll
        for (int q = 0; q < 8; q++) acc[q] = att0 * f[q];
    }

    #pragma unroll 8
    for (int s = 0; s < NSAMP; s++) {
        const float w = sc[nl][s];
        uint4 raw = *(const uint4*)(hin + (size_t)se[nl][s] * HDIM + lane * 8);
        h8_to_f8(raw, f);
        #pragma unroll
        for (int q = 0; q < 8; q++) acc[q] += w * f[q];
    }

    #pragma unroll
    for (int q = 0; q < 8; q++) acc[q] = fmaxf(acc[q], 0.0f);
    *(uint4*)(hout + (size_t)n * HDIM + lane * 8) = f8_to_h8(acc);
}

// ---------------------------------------------------------------------------
// Final: logits = h @ W2 + b2, then log_softmax over 40 classes.
// ---------------------------------------------------------------------------
__global__ void __launch_bounds__(128) final_kernel(
    const __half* __restrict__ h, const float* __restrict__ W2,
    const float* __restrict__ b2, float* __restrict__ out, int M)
{
    __shared__ float Ws[HDIM * CDIM];
    __shared__ float bs[CDIM];

    const int t = threadIdx.x;
    for (int i = t; i < HDIM * CDIM; i += 128) Ws[i] = W2[i];
    if (t < CDIM) bs[t] = b2[t];
    __syncthreads();

    const int row = blockIdx.x * 128 + t;
    if (row >= M) return;

    float acc[CDIM];
    #pragma unroll
    for (int c = 0; c < CDIM; c++) acc[c] = bs[c];

    const uint4* hp = (const uint4*)(h + (size_t)row * HDIM);
    for (int kc = 0; kc < HDIM / 8; kc++) {
        float f[8];
        h8_to_f8(hp[kc], f);
        #pragma unroll
        for (int kk = 0; kk < 8; kk++) {
            const float a = f[kk];
            const float* wr = &Ws[(kc * 8 + kk) * CDIM];
            #pragma unroll
            for (int c4 = 0; c4 < CDIM / 4; c4++) {
                float4 w = *(const float4*)&wr[c4 * 4];
                acc[c4 * 4 + 0] += a * w.x;
                acc[c4 * 4 + 1] += a * w.y;
                acc[c4 * 4 + 2] += a * w.z;
                acc[c4 * 4 + 3] += a * w.w;
            }
        }
    }

    float m = acc[0];
    #pragma unroll
    for (int c = 1; c < CDIM; c++) m = fmaxf(m, acc[c]);
    float s = 0.0f;
    #pragma unroll
    for (int c = 0; c < CDIM; c++) s += __expf(acc[c] - m);
    const float lse = m + __logf(s);

    float* op = out + (size_t)row * CDIM;
    #pragma unroll
    for (int c = 0; c < CDIM; c++) op[c] = acc[c] - lse;
}

// ---------------------------------------------------------------------------
// Launch sequence. Inputs: x, degree, ends, att, W0, b0, W1, b1, W2, b2
// ---------------------------------------------------------------------------
extern "C" void kernel_launch(void* const* d_in, const int* in_sizes, int n_in,
                              void* d_out, int out_size)
{
    const float* x   = (const float*)d_in[0];
    const float* deg = (const float*)d_in[1];
    const int*   ends= (const int*)  d_in[2];
    const float* att = (const float*)d_in[3];
    const float* W0  = (const float*)d_in[4];
    const float* b0  = (const float*)d_in[5];
    const float* W1  = (const float*)d_in[6];
    const float* b1  = (const float*)d_in[7];
    const float* W2  = (const float*)d_in[8];
    const float* b2  = (const float*)d_in[9];
    float* out = (float*)d_out;

    __half *bufA = nullptr, *bufB = nullptr;
    cudaGetSymbolAddress((void**)&bufA, g_bufA);
    cudaGetSymbolAddress((void**)&bufB, g_bufB);

    const int gridM   = (NNODES + 127) / 128;     // 782
    const int gridAgg = NNODES / NPB;             // 12500

    // Layer 0: h = x @ W0 + b0  -> bufA (fp16, tensor cores)
    hgemm_kernel<float><<<gridM, 256>>>(x, W0, b0, bufA, NNODES, 256);
    // Agg layer 0: bufA -> bufB (relu'd)
    agg_kernel<<<gridAgg, 128>>>(bufA, bufB,
                                 ends + 0 * (size_t)KHOPS * NNODES * RWS,
                                 deg, att + 0 * (KHOPS + 1));
    // Layer 1: h = bufB @ W1 + b1 -> bufA (fp16, tensor cores)
    hgemm_kernel<__half><<<gridM, 256>>>(bufB, W1, b1, bufA, NNODES, 128);
    // Agg layer 1: bufA -> bufB (relu'd)
    agg_kernel<<<gridAgg, 128>>>(bufA, bufB,
                                 ends + 1 * (size_t)KHOPS * NNODES * RWS,
                                 deg, att + 1 * (KHOPS + 1));
    // Final: logits + log_softmax -> out
    final_kernel<<<gridM, 128>>>(bufB, W2, b2, out, NNODES);
}